// round 2
// baseline (speedup 1.0000x reference)
#include <cuda_runtime.h>
#include <cstdint>

#define N_USERS 100000
#define N_ITEMS 40000
#define DIM     64
#define NTOT    (N_USERS + N_ITEMS)
#define VPR     (DIM / 4)          // float4 vectors per row = 16
#define NNZ_UI_MAX 1500000
#define NNZ_II_MAX 1000000
#define NNZ_UU_MAX 1500000

// -------- scratch (allocation-free: __device__ globals) --------
__device__ float4 g_ii1[N_ITEMS * VPR];
__device__ float4 g_uu1[N_USERS * VPR];
__device__ float4 g_ego_a[NTOT * VPR];
__device__ float4 g_ego_b[NTOT * VPR];
__device__ float4 g_acc[NTOT * VPR];

// CSR build scratch, per matrix
__device__ int    g_ptr_ui[NTOT + 1];
__device__ int    g_cur_ui[NTOT];
__device__ float2 g_pk_ui[NNZ_UI_MAX];   // (.x = int bits of col*VPR, .y = val)
__device__ int    g_ptr_ii[N_ITEMS + 1];
__device__ int    g_cur_ii[N_ITEMS];
__device__ float2 g_pk_ii[NNZ_II_MAX];
__device__ int    g_ptr_uu[N_USERS + 1];
__device__ int    g_cur_uu[N_USERS];
__device__ float2 g_pk_uu[NNZ_UU_MAX];

// -------- CSR build --------
__global__ __launch_bounds__(256) void k_zero_int(int* __restrict__ p, int n) {
    int i = blockIdx.x * blockDim.x + threadIdx.x;
    if (i < n) p[i] = 0;
}

__global__ __launch_bounds__(256) void k_hist(const int* __restrict__ rows,
                                              int* __restrict__ cnt, int nnz) {
    int i = blockIdx.x * blockDim.x + threadIdx.x;
    if (i < nnz) atomicAdd(cnt + __ldg(rows + i), 1);
}

// Single-block (1024 threads) exclusive scan over n counters, in place.
// Also copies the scanned offsets into cursor[] and writes cnt[n] = total.
__global__ __launch_bounds__(1024) void k_scan(int* __restrict__ cnt,
                                               int* __restrict__ cursor, int n) {
    __shared__ int sh[1024];
    int t = threadIdx.x;
    int chunk = (n + 1023) >> 10;
    int lo = t * chunk, hi = min(lo + chunk, n);
    int s = 0;
    for (int i = lo; i < hi; ++i) s += cnt[i];
    sh[t] = s;
    __syncthreads();
    #pragma unroll
    for (int off = 1; off < 1024; off <<= 1) {
        int v = (t >= off) ? sh[t - off] : 0;
        __syncthreads();
        sh[t] += v;
        __syncthreads();
    }
    int total = sh[1023];
    int run = (t == 0) ? 0 : sh[t - 1];
    for (int i = lo; i < hi; ++i) {
        int c = cnt[i];
        cnt[i] = run;
        cursor[i] = run;
        run += c;
    }
    if (t == 0) cnt[n] = total;
}

__global__ __launch_bounds__(256) void k_scatter(const int* __restrict__ rows,
                                                 const int* __restrict__ cols,
                                                 const float* __restrict__ vals,
                                                 int* __restrict__ cursor,
                                                 float2* __restrict__ pk, int nnz) {
    int i = blockIdx.x * blockDim.x + threadIdx.x;
    if (i >= nnz) return;
    int r = __ldg(rows + i);
    int c = __ldg(cols + i);
    float v = __ldg(vals + i);
    int pos = atomicAdd(cursor + r, 1);
    pk[pos] = make_float2(__int_as_float(c * VPR), v);
}

// -------- CSR gather SpMM: 16 threads per row, register accumulation --------
// y[r] = sum_j val_j * x[col_j];  if acc != nullptr: acc[r] += y[r]
__global__ __launch_bounds__(256) void k_spmm_csr(const int* __restrict__ ptr,
                                                  const float2* __restrict__ pk,
                                                  const float4* __restrict__ x,
                                                  float4* __restrict__ y,
                                                  float4* __restrict__ acc,
                                                  int nrows) {
    int r = blockIdx.x * 16 + (threadIdx.x >> 4);
    if (r >= nrows) return;
    int c = threadIdx.x & 15;
    int j = __ldg(ptr + r);
    int end = __ldg(ptr + r + 1);
    float4 s0 = make_float4(0.f, 0.f, 0.f, 0.f);
    float4 s1 = make_float4(0.f, 0.f, 0.f, 0.f);
    for (; j + 2 <= end; j += 2) {
        float2 p0 = __ldg(pk + j);
        float2 p1 = __ldg(pk + j + 1);
        float4 g0 = __ldg(x + __float_as_int(p0.x) + c);
        float4 g1 = __ldg(x + __float_as_int(p1.x) + c);
        s0.x += p0.y * g0.x; s0.y += p0.y * g0.y; s0.z += p0.y * g0.z; s0.w += p0.y * g0.w;
        s1.x += p1.y * g1.x; s1.y += p1.y * g1.y; s1.z += p1.y * g1.z; s1.w += p1.y * g1.w;
    }
    if (j < end) {
        float2 p0 = __ldg(pk + j);
        float4 g0 = __ldg(x + __float_as_int(p0.x) + c);
        s0.x += p0.y * g0.x; s0.y += p0.y * g0.y; s0.z += p0.y * g0.z; s0.w += p0.y * g0.w;
    }
    float4 s = make_float4(s0.x + s1.x, s0.y + s1.y, s0.z + s1.z, s0.w + s1.w);
    size_t idx = (size_t)r * VPR + c;
    y[idx] = s;
    if (acc) {
        float4 a = acc[idx];
        acc[idx] = make_float4(a.x + s.x, a.y + s.y, a.z + s.z, a.w + s.w);
    }
}

// ego = concat(user, item); acc = ego
__global__ __launch_bounds__(256) void k_init_ego(const float4* __restrict__ u,
                                                  const float4* __restrict__ it,
                                                  float4* __restrict__ ego,
                                                  float4* __restrict__ acc) {
    int i = blockIdx.x * blockDim.x + threadIdx.x;
    if (i >= NTOT * VPR) return;
    float4 v = (i < N_USERS * VPR) ? __ldg(u + i) : __ldg(it + (i - N_USERS * VPR));
    ego[i] = v;
    acc[i] = v;
}

// out = acc/4 + l2_normalize(g). One warp per row, float2 lanes.
__global__ __launch_bounds__(256) void k_finalize(const float2* __restrict__ acc,
                                                  const float2* __restrict__ g,
                                                  float2* __restrict__ out, int n_rows) {
    int w = (int)((blockIdx.x * (long long)blockDim.x + threadIdx.x) >> 5);
    int lane = threadIdx.x & 31;
    if (w >= n_rows) return;
    size_t idx = (size_t)w * 32 + lane;
    float2 gv = __ldg(g + idx);
    float s = gv.x * gv.x + gv.y * gv.y;
    #pragma unroll
    for (int o = 16; o; o >>= 1) s += __shfl_xor_sync(0xffffffffu, s, o);
    float scale = 1.0f / fmaxf(sqrtf(s), 1e-12f);
    float2 a = __ldg(acc + idx);
    out[idx] = make_float2(a.x * 0.25f + gv.x * scale,
                           a.y * 0.25f + gv.y * scale);
}

// -------- host orchestration --------
static inline int gridFor(long long threads, int tpb) {
    return (int)((threads + tpb - 1) / tpb);
}

extern "C" void kernel_launch(void* const* d_in, const int* in_sizes, int n_in,
                              void* d_out, int out_size) {
    const float4* user_emb = (const float4*)d_in[0];
    const float4* item_emb = (const float4*)d_in[1];
    const float4* uu_emb   = (const float4*)d_in[2];
    const float4* ii_emb   = (const float4*)d_in[3];
    const float*  ui_vals  = (const float*)d_in[4];
    const float*  ii_vals  = (const float*)d_in[5];
    const float*  uu_vals  = (const float*)d_in[6];
    const int*    ui_rows  = (const int*)d_in[7];
    const int*    ui_cols  = (const int*)d_in[8];
    const int*    ii_rows  = (const int*)d_in[9];
    const int*    ii_cols  = (const int*)d_in[10];
    const int*    uu_rows  = (const int*)d_in[11];
    const int*    uu_cols  = (const int*)d_in[12];
    const int nnz_ui = in_sizes[7];
    const int nnz_ii = in_sizes[9];
    const int nnz_uu = in_sizes[11];

    float* out = (float*)d_out;
    float4* out_u  = (float4*)out;
    float4* out_i  = (float4*)(out + (size_t)N_USERS * DIM);
    float4* out_ii = (float4*)(out + (size_t)(N_USERS + N_ITEMS) * DIM);
    float4* out_uu = (float4*)(out + (size_t)(N_USERS + 2 * N_ITEMS) * DIM);

    float4 *p_ii1, *p_uu1, *p_ego_a, *p_ego_b, *p_acc;
    cudaGetSymbolAddress((void**)&p_ii1,   g_ii1);
    cudaGetSymbolAddress((void**)&p_uu1,   g_uu1);
    cudaGetSymbolAddress((void**)&p_ego_a, g_ego_a);
    cudaGetSymbolAddress((void**)&p_ego_b, g_ego_b);
    cudaGetSymbolAddress((void**)&p_acc,   g_acc);
    int *ptr_ui, *cur_ui, *ptr_ii, *cur_ii, *ptr_uu, *cur_uu;
    float2 *pk_ui, *pk_ii, *pk_uu;
    cudaGetSymbolAddress((void**)&ptr_ui, g_ptr_ui);
    cudaGetSymbolAddress((void**)&cur_ui, g_cur_ui);
    cudaGetSymbolAddress((void**)&pk_ui,  g_pk_ui);
    cudaGetSymbolAddress((void**)&ptr_ii, g_ptr_ii);
    cudaGetSymbolAddress((void**)&cur_ii, g_cur_ii);
    cudaGetSymbolAddress((void**)&pk_ii,  g_pk_ii);
    cudaGetSymbolAddress((void**)&ptr_uu, g_ptr_uu);
    cudaGetSymbolAddress((void**)&cur_uu, g_cur_uu);
    cudaGetSymbolAddress((void**)&pk_uu,  g_pk_uu);

    const int TPB = 256;
    const int nEGv = NTOT * VPR;

    // ---- CSR builds (counting sort) ----
    k_zero_int<<<gridFor(NTOT + 1, TPB), TPB>>>(ptr_ui, NTOT + 1);
    k_hist<<<gridFor(nnz_ui, TPB), TPB>>>(ui_rows, ptr_ui, nnz_ui);
    k_scan<<<1, 1024>>>(ptr_ui, cur_ui, NTOT);
    k_scatter<<<gridFor(nnz_ui, TPB), TPB>>>(ui_rows, ui_cols, ui_vals, cur_ui, pk_ui, nnz_ui);

    k_zero_int<<<gridFor(N_ITEMS + 1, TPB), TPB>>>(ptr_ii, N_ITEMS + 1);
    k_hist<<<gridFor(nnz_ii, TPB), TPB>>>(ii_rows, ptr_ii, nnz_ii);
    k_scan<<<1, 1024>>>(ptr_ii, cur_ii, N_ITEMS);
    k_scatter<<<gridFor(nnz_ii, TPB), TPB>>>(ii_rows, ii_cols, ii_vals, cur_ii, pk_ii, nnz_ii);

    k_zero_int<<<gridFor(N_USERS + 1, TPB), TPB>>>(ptr_uu, N_USERS + 1);
    k_hist<<<gridFor(nnz_uu, TPB), TPB>>>(uu_rows, ptr_uu, nnz_uu);
    k_scan<<<1, 1024>>>(ptr_uu, cur_uu, N_USERS);
    k_scatter<<<gridFor(nnz_uu, TPB), TPB>>>(uu_rows, uu_cols, uu_vals, cur_uu, pk_uu, nnz_uu);

    // ---- ii chain (2 layers), last layer writes straight into d_out ----
    k_spmm_csr<<<gridFor(N_ITEMS, 16), TPB>>>(ptr_ii, pk_ii, ii_emb, p_ii1, nullptr, N_ITEMS);
    k_spmm_csr<<<gridFor(N_ITEMS, 16), TPB>>>(ptr_ii, pk_ii, p_ii1, out_ii, nullptr, N_ITEMS);

    // ---- uu chain (2 layers) ----
    k_spmm_csr<<<gridFor(N_USERS, 16), TPB>>>(ptr_uu, pk_uu, uu_emb, p_uu1, nullptr, N_USERS);
    k_spmm_csr<<<gridFor(N_USERS, 16), TPB>>>(ptr_uu, pk_uu, p_uu1, out_uu, nullptr, N_USERS);

    // ---- ui chain (3 layers, acc fused into SpMM epilogue) ----
    k_init_ego<<<gridFor(nEGv, TPB), TPB>>>(user_emb, item_emb, p_ego_a, p_acc);
    k_spmm_csr<<<gridFor(NTOT, 16), TPB>>>(ptr_ui, pk_ui, p_ego_a, p_ego_b, p_acc, NTOT);
    k_spmm_csr<<<gridFor(NTOT, 16), TPB>>>(ptr_ui, pk_ui, p_ego_b, p_ego_a, p_acc, NTOT);
    k_spmm_csr<<<gridFor(NTOT, 16), TPB>>>(ptr_ui, pk_ui, p_ego_a, p_ego_b, p_acc, NTOT);

    // ---- finalize ----
    k_finalize<<<gridFor((long long)N_USERS * 32, TPB), TPB>>>(
        (const float2*)p_acc, (const float2*)out_uu, (float2*)out_u, N_USERS);
    k_finalize<<<gridFor((long long)N_ITEMS * 32, TPB), TPB>>>(
        (const float2*)p_acc + (size_t)N_USERS * 32, (const float2*)out_ii,
        (float2*)out_i, N_ITEMS);
}

// round 3
// speedup vs baseline: 1.4585x; 1.4585x over previous
#include <cuda_runtime.h>
#include <cstdint>

#define N_USERS 100000
#define N_ITEMS 40000
#define DIM     64
#define NTOT    (N_USERS + N_ITEMS)
#define VPR     (DIM / 4)          // float4 vectors per row = 16
#define NNZ_UI_MAX 1500000
#define NNZ_II_MAX 1000000
#define NNZ_UU_MAX 1500000

// -------- scratch (allocation-free: __device__ globals) --------
__device__ float4 g_ii1[N_ITEMS * VPR];
__device__ float4 g_uu1[N_USERS * VPR];
__device__ float4 g_ego_a[NTOT * VPR];
__device__ float4 g_ego_b[NTOT * VPR];
__device__ float4 g_acc[NTOT * VPR];

__device__ int    g_ptr_ui[NTOT + 1];
__device__ int    g_cur_ui[NTOT];
__device__ float2 g_pk_ui[NNZ_UI_MAX];   // (.x = int bits of col*VPR, .y = val)
__device__ int    g_ptr_ii[N_ITEMS + 1];
__device__ int    g_cur_ii[N_ITEMS];
__device__ float2 g_pk_ii[NNZ_II_MAX];
__device__ int    g_ptr_uu[N_USERS + 1];
__device__ int    g_cur_uu[N_USERS];
__device__ float2 g_pk_uu[NNZ_UU_MAX];

// -------- fused CSR build --------
__global__ __launch_bounds__(256) void k_zero3(int* __restrict__ a, int na,
                                               int* __restrict__ b, int nb,
                                               int* __restrict__ c, int nc) {
    int i = blockIdx.x * blockDim.x + threadIdx.x;
    if (i < na) a[i] = 0;
    if (i < nb) b[i] = 0;
    if (i < nc) c[i] = 0;
}

__global__ __launch_bounds__(256) void k_hist3(const int* __restrict__ r0, int n0, int* __restrict__ c0,
                                               const int* __restrict__ r1, int n1, int* __restrict__ c1,
                                               const int* __restrict__ r2, int n2, int* __restrict__ c2) {
    int i = blockIdx.x * blockDim.x + threadIdx.x;
    if (i < n0) atomicAdd(c0 + __ldg(r0 + i), 1);
    if (i < n1) atomicAdd(c1 + __ldg(r1 + i), 1);
    if (i < n2) atomicAdd(c2 + __ldg(r2 + i), 1);
}

// 3 blocks, one per matrix: exclusive scan of cnt in place, copy into cursor,
// cnt[n] = total.
__global__ __launch_bounds__(1024) void k_scan3(int* __restrict__ cA, int* __restrict__ uA, int nA,
                                                int* __restrict__ cB, int* __restrict__ uB, int nB,
                                                int* __restrict__ cC, int* __restrict__ uC, int nC) {
    int* cnt;
    int* cursor;
    int n;
    if (blockIdx.x == 0) { cnt = cA; cursor = uA; n = nA; }
    else if (blockIdx.x == 1) { cnt = cB; cursor = uB; n = nB; }
    else { cnt = cC; cursor = uC; n = nC; }

    __shared__ int sh[1024];
    int t = threadIdx.x;
    int chunk = (n + 1023) >> 10;
    int lo = t * chunk, hi = min(lo + chunk, n);
    int s = 0;
    for (int i = lo; i < hi; ++i) s += cnt[i];
    sh[t] = s;
    __syncthreads();
    #pragma unroll
    for (int off = 1; off < 1024; off <<= 1) {
        int v = (t >= off) ? sh[t - off] : 0;
        __syncthreads();
        sh[t] += v;
        __syncthreads();
    }
    int total = sh[1023];
    int run = (t == 0) ? 0 : sh[t - 1];
    for (int i = lo; i < hi; ++i) {
        int c = cnt[i];
        cnt[i] = run;
        cursor[i] = run;
        run += c;
    }
    if (t == 0) cnt[n] = total;
}

__global__ __launch_bounds__(256) void k_scatter3(
        const int* __restrict__ r0, const int* __restrict__ c0, const float* __restrict__ v0,
        int* __restrict__ u0, float2* __restrict__ p0, int n0,
        const int* __restrict__ r1, const int* __restrict__ c1, const float* __restrict__ v1,
        int* __restrict__ u1, float2* __restrict__ p1, int n1,
        const int* __restrict__ r2, const int* __restrict__ c2, const float* __restrict__ v2,
        int* __restrict__ u2, float2* __restrict__ p2, int n2) {
    int i = blockIdx.x * blockDim.x + threadIdx.x;
    if (i < n0) {
        int pos = atomicAdd(u0 + __ldg(r0 + i), 1);
        p0[pos] = make_float2(__int_as_float(__ldg(c0 + i) * VPR), __ldg(v0 + i));
    }
    if (i < n1) {
        int pos = atomicAdd(u1 + __ldg(r1 + i), 1);
        p1[pos] = make_float2(__int_as_float(__ldg(c1 + i) * VPR), __ldg(v1 + i));
    }
    if (i < n2) {
        int pos = atomicAdd(u2 + __ldg(r2 + i), 1);
        p2[pos] = make_float2(__int_as_float(__ldg(c2 + i) * VPR), __ldg(v2 + i));
    }
}

// -------- CSR gather SpMM, high-MLP --------
// 16 lanes per row. Batch-load 16 packed entries coalesced, shuffle-broadcast,
// 4 independent gathers in flight per step.
// y[r] = sum_j val_j * x[col_j];  if acc: acc[r] += y[r]
__global__ __launch_bounds__(256) void k_spmm_csr(const int* __restrict__ ptr,
                                                  const float2* __restrict__ pk,
                                                  const float4* __restrict__ x,
                                                  float4* __restrict__ y,
                                                  float4* __restrict__ acc,
                                                  int nrows) {
    int r = blockIdx.x * 16 + (threadIdx.x >> 4);
    int c = threadIdx.x & 15;
    unsigned gmask = 0xFFFFu << (threadIdx.x & 16);   // this half-warp's lanes
    if (r >= nrows) return;
    int j = __ldg(ptr + r);
    int end = __ldg(ptr + r + 1);
    float4 s = make_float4(0.f, 0.f, 0.f, 0.f);
    while (j < end) {
        int nb = min(16, end - j);
        float2 p = (c < nb) ? __ldg(pk + j + c) : make_float2(0.f, 0.f);
        int k = 0;
        for (; k + 4 <= nb; k += 4) {
            int   i0 = __shfl_sync(gmask, __float_as_int(p.x), k + 0, 16);
            int   i1 = __shfl_sync(gmask, __float_as_int(p.x), k + 1, 16);
            int   i2 = __shfl_sync(gmask, __float_as_int(p.x), k + 2, 16);
            int   i3 = __shfl_sync(gmask, __float_as_int(p.x), k + 3, 16);
            float v0 = __shfl_sync(gmask, p.y, k + 0, 16);
            float v1 = __shfl_sync(gmask, p.y, k + 1, 16);
            float v2 = __shfl_sync(gmask, p.y, k + 2, 16);
            float v3 = __shfl_sync(gmask, p.y, k + 3, 16);
            float4 g0 = __ldg(x + i0 + c);
            float4 g1 = __ldg(x + i1 + c);
            float4 g2 = __ldg(x + i2 + c);
            float4 g3 = __ldg(x + i3 + c);
            s.x += v0 * g0.x; s.y += v0 * g0.y; s.z += v0 * g0.z; s.w += v0 * g0.w;
            s.x += v1 * g1.x; s.y += v1 * g1.y; s.z += v1 * g1.z; s.w += v1 * g1.w;
            s.x += v2 * g2.x; s.y += v2 * g2.y; s.z += v2 * g2.z; s.w += v2 * g2.w;
            s.x += v3 * g3.x; s.y += v3 * g3.y; s.z += v3 * g3.z; s.w += v3 * g3.w;
        }
        if (k + 2 <= nb) {
            int   i0 = __shfl_sync(gmask, __float_as_int(p.x), k + 0, 16);
            int   i1 = __shfl_sync(gmask, __float_as_int(p.x), k + 1, 16);
            float v0 = __shfl_sync(gmask, p.y, k + 0, 16);
            float v1 = __shfl_sync(gmask, p.y, k + 1, 16);
            float4 g0 = __ldg(x + i0 + c);
            float4 g1 = __ldg(x + i1 + c);
            s.x += v0 * g0.x; s.y += v0 * g0.y; s.z += v0 * g0.z; s.w += v0 * g0.w;
            s.x += v1 * g1.x; s.y += v1 * g1.y; s.z += v1 * g1.z; s.w += v1 * g1.w;
            k += 2;
        }
        if (k < nb) {
            int   i0 = __shfl_sync(gmask, __float_as_int(p.x), k, 16);
            float v0 = __shfl_sync(gmask, p.y, k, 16);
            float4 g0 = __ldg(x + i0 + c);
            s.x += v0 * g0.x; s.y += v0 * g0.y; s.z += v0 * g0.z; s.w += v0 * g0.w;
        }
        j += nb;
    }
    size_t idx = (size_t)r * VPR + c;
    y[idx] = s;
    if (acc) {
        float4 a = acc[idx];
        acc[idx] = make_float4(a.x + s.x, a.y + s.y, a.z + s.z, a.w + s.w);
    }
}

// ego = concat(user, item); acc = ego
__global__ __launch_bounds__(256) void k_init_ego(const float4* __restrict__ u,
                                                  const float4* __restrict__ it,
                                                  float4* __restrict__ ego,
                                                  float4* __restrict__ acc) {
    int i = blockIdx.x * blockDim.x + threadIdx.x;
    if (i >= NTOT * VPR) return;
    float4 v = (i < N_USERS * VPR) ? __ldg(u + i) : __ldg(it + (i - N_USERS * VPR));
    ego[i] = v;
    acc[i] = v;
}

// out = acc/4 + l2_normalize(g). One warp per row, float2 lanes.
__global__ __launch_bounds__(256) void k_finalize(const float2* __restrict__ acc,
                                                  const float2* __restrict__ g,
                                                  float2* __restrict__ out, int n_rows) {
    int w = (int)((blockIdx.x * (long long)blockDim.x + threadIdx.x) >> 5);
    int lane = threadIdx.x & 31;
    if (w >= n_rows) return;
    size_t idx = (size_t)w * 32 + lane;
    float2 gv = __ldg(g + idx);
    float s = gv.x * gv.x + gv.y * gv.y;
    #pragma unroll
    for (int o = 16; o; o >>= 1) s += __shfl_xor_sync(0xffffffffu, s, o);
    float scale = 1.0f / fmaxf(sqrtf(s), 1e-12f);
    float2 a = __ldg(acc + idx);
    out[idx] = make_float2(a.x * 0.25f + gv.x * scale,
                           a.y * 0.25f + gv.y * scale);
}

// -------- host orchestration --------
static inline int gridFor(long long threads, int tpb) {
    return (int)((threads + tpb - 1) / tpb);
}

extern "C" void kernel_launch(void* const* d_in, const int* in_sizes, int n_in,
                              void* d_out, int out_size) {
    const float4* user_emb = (const float4*)d_in[0];
    const float4* item_emb = (const float4*)d_in[1];
    const float4* uu_emb   = (const float4*)d_in[2];
    const float4* ii_emb   = (const float4*)d_in[3];
    const float*  ui_vals  = (const float*)d_in[4];
    const float*  ii_vals  = (const float*)d_in[5];
    const float*  uu_vals  = (const float*)d_in[6];
    const int*    ui_rows  = (const int*)d_in[7];
    const int*    ui_cols  = (const int*)d_in[8];
    const int*    ii_rows  = (const int*)d_in[9];
    const int*    ii_cols  = (const int*)d_in[10];
    const int*    uu_rows  = (const int*)d_in[11];
    const int*    uu_cols  = (const int*)d_in[12];
    const int nnz_ui = in_sizes[7];
    const int nnz_ii = in_sizes[9];
    const int nnz_uu = in_sizes[11];

    float* out = (float*)d_out;
    float4* out_u  = (float4*)out;
    float4* out_i  = (float4*)(out + (size_t)N_USERS * DIM);
    float4* out_ii = (float4*)(out + (size_t)(N_USERS + N_ITEMS) * DIM);
    float4* out_uu = (float4*)(out + (size_t)(N_USERS + 2 * N_ITEMS) * DIM);

    float4 *p_ii1, *p_uu1, *p_ego_a, *p_ego_b, *p_acc;
    cudaGetSymbolAddress((void**)&p_ii1,   g_ii1);
    cudaGetSymbolAddress((void**)&p_uu1,   g_uu1);
    cudaGetSymbolAddress((void**)&p_ego_a, g_ego_a);
    cudaGetSymbolAddress((void**)&p_ego_b, g_ego_b);
    cudaGetSymbolAddress((void**)&p_acc,   g_acc);
    int *ptr_ui, *cur_ui, *ptr_ii, *cur_ii, *ptr_uu, *cur_uu;
    float2 *pk_ui, *pk_ii, *pk_uu;
    cudaGetSymbolAddress((void**)&ptr_ui, g_ptr_ui);
    cudaGetSymbolAddress((void**)&cur_ui, g_cur_ui);
    cudaGetSymbolAddress((void**)&pk_ui,  g_pk_ui);
    cudaGetSymbolAddress((void**)&ptr_ii, g_ptr_ii);
    cudaGetSymbolAddress((void**)&cur_ii, g_cur_ii);
    cudaGetSymbolAddress((void**)&pk_ii,  g_pk_ii);
    cudaGetSymbolAddress((void**)&ptr_uu, g_ptr_uu);
    cudaGetSymbolAddress((void**)&cur_uu, g_cur_uu);
    cudaGetSymbolAddress((void**)&pk_uu,  g_pk_uu);

    const int TPB = 256;
    const int nEGv = NTOT * VPR;
    const int nnz_max = max(max(nnz_ui, nnz_ii), nnz_uu);

    // ---- fused CSR build ----
    k_zero3<<<gridFor(NTOT + 1, TPB), TPB>>>(ptr_ui, NTOT + 1,
                                             ptr_ii, N_ITEMS + 1,
                                             ptr_uu, N_USERS + 1);
    k_hist3<<<gridFor(nnz_max, TPB), TPB>>>(ui_rows, nnz_ui, ptr_ui,
                                            ii_rows, nnz_ii, ptr_ii,
                                            uu_rows, nnz_uu, ptr_uu);
    k_scan3<<<3, 1024>>>(ptr_ui, cur_ui, NTOT,
                         ptr_ii, cur_ii, N_ITEMS,
                         ptr_uu, cur_uu, N_USERS);
    k_scatter3<<<gridFor(nnz_max, TPB), TPB>>>(
        ui_rows, ui_cols, ui_vals, cur_ui, pk_ui, nnz_ui,
        ii_rows, ii_cols, ii_vals, cur_ii, pk_ii, nnz_ii,
        uu_rows, uu_cols, uu_vals, cur_uu, pk_uu, nnz_uu);

    // ---- ii chain (2 layers), last layer writes straight into d_out ----
    k_spmm_csr<<<gridFor(N_ITEMS, 16), TPB>>>(ptr_ii, pk_ii, ii_emb, p_ii1, nullptr, N_ITEMS);
    k_spmm_csr<<<gridFor(N_ITEMS, 16), TPB>>>(ptr_ii, pk_ii, p_ii1, out_ii, nullptr, N_ITEMS);

    // ---- uu chain (2 layers) ----
    k_spmm_csr<<<gridFor(N_USERS, 16), TPB>>>(ptr_uu, pk_uu, uu_emb, p_uu1, nullptr, N_USERS);
    k_spmm_csr<<<gridFor(N_USERS, 16), TPB>>>(ptr_uu, pk_uu, p_uu1, out_uu, nullptr, N_USERS);

    // ---- ui chain (3 layers, acc fused into SpMM epilogue) ----
    k_init_ego<<<gridFor(nEGv, TPB), TPB>>>(user_emb, item_emb, p_ego_a, p_acc);
    k_spmm_csr<<<gridFor(NTOT, 16), TPB>>>(ptr_ui, pk_ui, p_ego_a, p_ego_b, p_acc, NTOT);
    k_spmm_csr<<<gridFor(NTOT, 16), TPB>>>(ptr_ui, pk_ui, p_ego_b, p_ego_a, p_acc, NTOT);
    k_spmm_csr<<<gridFor(NTOT, 16), TPB>>>(ptr_ui, pk_ui, p_ego_a, p_ego_b, p_acc, NTOT);

    // ---- finalize ----
    k_finalize<<<gridFor((long long)N_USERS * 32, TPB), TPB>>>(
        (const float2*)p_acc, (const float2*)out_uu, (float2*)out_u, N_USERS);
    k_finalize<<<gridFor((long long)N_ITEMS * 32, TPB), TPB>>>(
        (const float2*)p_acc + (size_t)N_USERS * 32, (const float2*)out_ii,
        (float2*)out_i, N_ITEMS);
}

// round 4
// speedup vs baseline: 1.7428x; 1.1949x over previous
#include <cuda_runtime.h>
#include <cstdint>

#define N_USERS 100000
#define N_ITEMS 40000
#define DIM     64
#define NTOT    (N_USERS + N_ITEMS)
#define VPR     (DIM / 4)          // float4 vectors per row = 16
#define NNZ_UI_MAX 1500000
#define NNZ_II_MAX 1000000
#define NNZ_UU_MAX 1500000

#define B_II  (N_ITEMS / 16)       // 2500 blocks, 16 rows each
#define B_UU  (N_USERS / 16)       // 6250
#define B_UI  (NTOT / 16)          // 8750
#define B_EGO ((NTOT * VPR + 255) / 256)  // 8750

// -------- scratch (allocation-free: __device__ globals) --------
__device__ float4 g_ii1[N_ITEMS * VPR];
__device__ float4 g_uu1[N_USERS * VPR];
__device__ float4 g_ego_a[NTOT * VPR];
__device__ float4 g_ego_b[NTOT * VPR];
__device__ float4 g_acc[NTOT * VPR];

__device__ int    g_ptr_ui[NTOT + 1];
__device__ float2 g_pk_ui[NNZ_UI_MAX];   // (.x = int bits of col*VPR, .y = val)
__device__ int    g_rk_ui[NNZ_UI_MAX];
__device__ int    g_ptr_ii[N_ITEMS + 1];
__device__ float2 g_pk_ii[NNZ_II_MAX];
__device__ int    g_rk_ii[NNZ_II_MAX];
__device__ int    g_ptr_uu[N_USERS + 1];
__device__ float2 g_pk_uu[NNZ_UU_MAX];
__device__ int    g_rk_uu[NNZ_UU_MAX];

// -------- fused CSR build --------
__global__ __launch_bounds__(256) void k_zero3(int* __restrict__ a, int na,
                                               int* __restrict__ b, int nb,
                                               int* __restrict__ c, int nc) {
    int i = blockIdx.x * blockDim.x + threadIdx.x;
    if (i < na) a[i] = 0;
    if (i < nb) b[i] = 0;
    if (i < nc) c[i] = 0;
}

// histogram + record each edge's within-row rank (atomic return value)
__global__ __launch_bounds__(256) void k_hist3(
        const int* __restrict__ r0, int n0, int* __restrict__ c0, int* __restrict__ k0,
        const int* __restrict__ r1, int n1, int* __restrict__ c1, int* __restrict__ k1,
        const int* __restrict__ r2, int n2, int* __restrict__ c2, int* __restrict__ k2) {
    int i = blockIdx.x * blockDim.x + threadIdx.x;
    if (i < n0) k0[i] = atomicAdd(c0 + __ldg(r0 + i), 1);
    if (i < n1) k1[i] = atomicAdd(c1 + __ldg(r1 + i), 1);
    if (i < n2) k2[i] = atomicAdd(c2 + __ldg(r2 + i), 1);
}

// 3 blocks, one per matrix: exclusive scan of cnt in place, cnt[n] = total.
__global__ __launch_bounds__(1024) void k_scan3(int* __restrict__ cA, int nA,
                                                int* __restrict__ cB, int nB,
                                                int* __restrict__ cC, int nC) {
    int* cnt; int n;
    if (blockIdx.x == 0) { cnt = cA; n = nA; }
    else if (blockIdx.x == 1) { cnt = cB; n = nB; }
    else { cnt = cC; n = nC; }

    __shared__ int sh[1024];
    int t = threadIdx.x;
    int chunk = (n + 1023) >> 10;
    int lo = t * chunk, hi = min(lo + chunk, n);
    int s = 0;
    for (int i = lo; i < hi; ++i) s += cnt[i];
    sh[t] = s;
    __syncthreads();
    #pragma unroll
    for (int off = 1; off < 1024; off <<= 1) {
        int v = (t >= off) ? sh[t - off] : 0;
        __syncthreads();
        sh[t] += v;
        __syncthreads();
    }
    int total = sh[1023];
    int run = (t == 0) ? 0 : sh[t - 1];
    for (int i = lo; i < hi; ++i) {
        int c = cnt[i];
        cnt[i] = run;
        run += c;
    }
    if (t == 0) cnt[n] = total;
}

// scatter without atomics: pos = ptr[row] + rank[i]
__global__ __launch_bounds__(256) void k_scatter3(
        const int* __restrict__ r0, const int* __restrict__ c0, const float* __restrict__ v0,
        const int* __restrict__ ptr0, const int* __restrict__ k0, float2* __restrict__ p0, int n0,
        const int* __restrict__ r1, const int* __restrict__ c1, const float* __restrict__ v1,
        const int* __restrict__ ptr1, const int* __restrict__ k1, float2* __restrict__ p1, int n1,
        const int* __restrict__ r2, const int* __restrict__ c2, const float* __restrict__ v2,
        const int* __restrict__ ptr2, const int* __restrict__ k2, float2* __restrict__ p2, int n2) {
    int i = blockIdx.x * blockDim.x + threadIdx.x;
    if (i < n0) {
        int pos = __ldg(ptr0 + __ldg(r0 + i)) + __ldg(k0 + i);
        p0[pos] = make_float2(__int_as_float(__ldg(c0 + i) * VPR), __ldg(v0 + i));
    }
    if (i < n1) {
        int pos = __ldg(ptr1 + __ldg(r1 + i)) + __ldg(k1 + i);
        p1[pos] = make_float2(__int_as_float(__ldg(c1 + i) * VPR), __ldg(v1 + i));
    }
    if (i < n2) {
        int pos = __ldg(ptr2 + __ldg(r2 + i)) + __ldg(k2 + i);
        p2[pos] = make_float2(__int_as_float(__ldg(c2 + i) * VPR), __ldg(v2 + i));
    }
}

// -------- CSR gather SpMM core: 16 lanes/row, uniform pk loads, unroll 4 --------
__device__ __forceinline__ float4 spmm_row_sum(const int* __restrict__ ptr,
                                               const float2* __restrict__ pk,
                                               const float4* __restrict__ x,
                                               int r, int c) {
    int j = __ldg(ptr + r);
    int end = __ldg(ptr + r + 1);
    float4 s = make_float4(0.f, 0.f, 0.f, 0.f);
    for (; j + 4 <= end; j += 4) {
        float2 p0 = __ldg(pk + j + 0);
        float2 p1 = __ldg(pk + j + 1);
        float2 p2 = __ldg(pk + j + 2);
        float2 p3 = __ldg(pk + j + 3);
        float4 g0 = __ldg(x + __float_as_int(p0.x) + c);
        float4 g1 = __ldg(x + __float_as_int(p1.x) + c);
        float4 g2 = __ldg(x + __float_as_int(p2.x) + c);
        float4 g3 = __ldg(x + __float_as_int(p3.x) + c);
        s.x += p0.y * g0.x; s.y += p0.y * g0.y; s.z += p0.y * g0.z; s.w += p0.y * g0.w;
        s.x += p1.y * g1.x; s.y += p1.y * g1.y; s.z += p1.y * g1.z; s.w += p1.y * g1.w;
        s.x += p2.y * g2.x; s.y += p2.y * g2.y; s.z += p2.y * g2.z; s.w += p2.y * g2.w;
        s.x += p3.y * g3.x; s.y += p3.y * g3.y; s.z += p3.y * g3.z; s.w += p3.y * g3.w;
    }
    for (; j < end; ++j) {
        float2 p0 = __ldg(pk + j);
        float4 g0 = __ldg(x + __float_as_int(p0.x) + c);
        s.x += p0.y * g0.x; s.y += p0.y * g0.y; s.z += p0.y * g0.z; s.w += p0.y * g0.w;
    }
    return s;
}

__device__ __forceinline__ void spmm_block(const int* __restrict__ ptr,
                                           const float2* __restrict__ pk,
                                           const float4* __restrict__ x,
                                           float4* __restrict__ y,
                                           float4* __restrict__ acc,
                                           int blk) {
    int r = blk * 16 + (threadIdx.x >> 4);
    int c = threadIdx.x & 15;
    float4 s = spmm_row_sum(ptr, pk, x, r, c);
    size_t idx = (size_t)r * VPR + c;
    y[idx] = s;
    if (acc) {
        float4 a = acc[idx];
        acc[idx] = make_float4(a.x + s.x, a.y + s.y, a.z + s.z, a.w + s.w);
    }
}

// mix1: ii layer1 | uu layer1 | init_ego (all independent)
__global__ __launch_bounds__(256) void k_mix1(const int* __restrict__ ptr_ii,
                                              const float2* __restrict__ pk_ii,
                                              const float4* __restrict__ ii_emb,
                                              float4* __restrict__ ii1,
                                              const int* __restrict__ ptr_uu,
                                              const float2* __restrict__ pk_uu,
                                              const float4* __restrict__ uu_emb,
                                              float4* __restrict__ uu1,
                                              const float4* __restrict__ u_emb,
                                              const float4* __restrict__ it_emb,
                                              float4* __restrict__ ego,
                                              float4* __restrict__ acc) {
    int b = blockIdx.x;
    if (b < B_II) {
        spmm_block(ptr_ii, pk_ii, ii_emb, ii1, nullptr, b);
    } else if (b < B_II + B_UU) {
        spmm_block(ptr_uu, pk_uu, uu_emb, uu1, nullptr, b - B_II);
    } else {
        int i = (b - B_II - B_UU) * 256 + threadIdx.x;
        if (i < NTOT * VPR) {
            float4 v = (i < N_USERS * VPR) ? __ldg(u_emb + i)
                                           : __ldg(it_emb + (i - N_USERS * VPR));
            ego[i] = v;
            acc[i] = v;
        }
    }
}

// mix2: ii layer2 -> out_ii | uu layer2 -> out_uu | ui layer1 (acc fused)
__global__ __launch_bounds__(256) void k_mix2(const int* __restrict__ ptr_ii,
                                              const float2* __restrict__ pk_ii,
                                              const float4* __restrict__ ii1,
                                              float4* __restrict__ out_ii,
                                              const int* __restrict__ ptr_uu,
                                              const float2* __restrict__ pk_uu,
                                              const float4* __restrict__ uu1,
                                              float4* __restrict__ out_uu,
                                              const int* __restrict__ ptr_ui,
                                              const float2* __restrict__ pk_ui,
                                              const float4* __restrict__ ego_a,
                                              float4* __restrict__ ego_b,
                                              float4* __restrict__ acc) {
    int b = blockIdx.x;
    if (b < B_II) {
        spmm_block(ptr_ii, pk_ii, ii1, out_ii, nullptr, b);
    } else if (b < B_II + B_UU) {
        spmm_block(ptr_uu, pk_uu, uu1, out_uu, nullptr, b - B_II);
    } else {
        spmm_block(ptr_ui, pk_ui, ego_a, ego_b, acc, b - B_II - B_UU);
    }
}

// ui layer2
__global__ __launch_bounds__(256) void k_ui2(const int* __restrict__ ptr_ui,
                                             const float2* __restrict__ pk_ui,
                                             const float4* __restrict__ ego_b,
                                             float4* __restrict__ ego_a,
                                             float4* __restrict__ acc) {
    spmm_block(ptr_ui, pk_ui, ego_b, ego_a, acc, blockIdx.x);
}

// ui layer3 fused with finalize:
// out = (acc + s)/4 + l2_normalize(g), g = out_uu row (users) / out_ii row (items)
__global__ __launch_bounds__(256) void k_ui3(const int* __restrict__ ptr_ui,
                                             const float2* __restrict__ pk_ui,
                                             const float4* __restrict__ ego_a,
                                             const float4* __restrict__ acc,
                                             const float4* __restrict__ out_uu,
                                             const float4* __restrict__ out_ii,
                                             float4* __restrict__ out_u,
                                             float4* __restrict__ out_i) {
    int r = blockIdx.x * 16 + (threadIdx.x >> 4);
    int c = threadIdx.x & 15;
    float4 s = spmm_row_sum(ptr_ui, pk_ui, ego_a, r, c);
    size_t idx = (size_t)r * VPR + c;
    float4 a = __ldg(acc + idx);
    float ax = (a.x + s.x) * 0.25f;
    float ay = (a.y + s.y) * 0.25f;
    float az = (a.z + s.z) * 0.25f;
    float aw = (a.w + s.w) * 0.25f;

    const float4* g = (r < N_USERS) ? (out_uu + (size_t)r * VPR)
                                    : (out_ii + (size_t)(r - N_USERS) * VPR);
    float4 gv = __ldg(g + c);
    float d = gv.x * gv.x + gv.y * gv.y + gv.z * gv.z + gv.w * gv.w;
    #pragma unroll
    for (int o = 8; o; o >>= 1) d += __shfl_xor_sync(0xffffffffu, d, o, 16);
    float scale = 1.0f / fmaxf(sqrtf(d), 1e-12f);

    float4* o = (r < N_USERS) ? (out_u + (size_t)r * VPR)
                              : (out_i + (size_t)(r - N_USERS) * VPR);
    o[c] = make_float4(ax + gv.x * scale, ay + gv.y * scale,
                       az + gv.z * scale, aw + gv.w * scale);
}

// -------- host orchestration --------
static inline int gridFor(long long threads, int tpb) {
    return (int)((threads + tpb - 1) / tpb);
}

extern "C" void kernel_launch(void* const* d_in, const int* in_sizes, int n_in,
                              void* d_out, int out_size) {
    const float4* user_emb = (const float4*)d_in[0];
    const float4* item_emb = (const float4*)d_in[1];
    const float4* uu_emb   = (const float4*)d_in[2];
    const float4* ii_emb   = (const float4*)d_in[3];
    const float*  ui_vals  = (const float*)d_in[4];
    const float*  ii_vals  = (const float*)d_in[5];
    const float*  uu_vals  = (const float*)d_in[6];
    const int*    ui_rows  = (const int*)d_in[7];
    const int*    ui_cols  = (const int*)d_in[8];
    const int*    ii_rows  = (const int*)d_in[9];
    const int*    ii_cols  = (const int*)d_in[10];
    const int*    uu_rows  = (const int*)d_in[11];
    const int*    uu_cols  = (const int*)d_in[12];
    const int nnz_ui = in_sizes[7];
    const int nnz_ii = in_sizes[9];
    const int nnz_uu = in_sizes[11];

    float* out = (float*)d_out;
    float4* out_u  = (float4*)out;
    float4* out_i  = (float4*)(out + (size_t)N_USERS * DIM);
    float4* out_ii = (float4*)(out + (size_t)(N_USERS + N_ITEMS) * DIM);
    float4* out_uu = (float4*)(out + (size_t)(N_USERS + 2 * N_ITEMS) * DIM);

    float4 *p_ii1, *p_uu1, *p_ego_a, *p_ego_b, *p_acc;
    cudaGetSymbolAddress((void**)&p_ii1,   g_ii1);
    cudaGetSymbolAddress((void**)&p_uu1,   g_uu1);
    cudaGetSymbolAddress((void**)&p_ego_a, g_ego_a);
    cudaGetSymbolAddress((void**)&p_ego_b, g_ego_b);
    cudaGetSymbolAddress((void**)&p_acc,   g_acc);
    int *ptr_ui, *ptr_ii, *ptr_uu, *rk_ui, *rk_ii, *rk_uu;
    float2 *pk_ui, *pk_ii, *pk_uu;
    cudaGetSymbolAddress((void**)&ptr_ui, g_ptr_ui);
    cudaGetSymbolAddress((void**)&pk_ui,  g_pk_ui);
    cudaGetSymbolAddress((void**)&rk_ui,  g_rk_ui);
    cudaGetSymbolAddress((void**)&ptr_ii, g_ptr_ii);
    cudaGetSymbolAddress((void**)&pk_ii,  g_pk_ii);
    cudaGetSymbolAddress((void**)&rk_ii,  g_rk_ii);
    cudaGetSymbolAddress((void**)&ptr_uu, g_ptr_uu);
    cudaGetSymbolAddress((void**)&pk_uu,  g_pk_uu);
    cudaGetSymbolAddress((void**)&rk_uu,  g_rk_uu);

    const int TPB = 256;
    const int nnz_max = max(max(nnz_ui, nnz_ii), nnz_uu);

    // ---- fused CSR build (atomic-free scatter) ----
    k_zero3<<<gridFor(NTOT + 1, TPB), TPB>>>(ptr_ui, NTOT + 1,
                                             ptr_ii, N_ITEMS + 1,
                                             ptr_uu, N_USERS + 1);
    k_hist3<<<gridFor(nnz_max, TPB), TPB>>>(ui_rows, nnz_ui, ptr_ui, rk_ui,
                                            ii_rows, nnz_ii, ptr_ii, rk_ii,
                                            uu_rows, nnz_uu, ptr_uu, rk_uu);
    k_scan3<<<3, 1024>>>(ptr_ui, NTOT, ptr_ii, N_ITEMS, ptr_uu, N_USERS);
    k_scatter3<<<gridFor(nnz_max, TPB), TPB>>>(
        ui_rows, ui_cols, ui_vals, ptr_ui, rk_ui, pk_ui, nnz_ui,
        ii_rows, ii_cols, ii_vals, ptr_ii, rk_ii, pk_ii, nnz_ii,
        uu_rows, uu_cols, uu_vals, ptr_uu, rk_uu, pk_uu, nnz_uu);

    // ---- propagation ----
    k_mix1<<<B_II + B_UU + B_EGO, TPB>>>(ptr_ii, pk_ii, ii_emb, p_ii1,
                                         ptr_uu, pk_uu, uu_emb, p_uu1,
                                         user_emb, item_emb, p_ego_a, p_acc);
    k_mix2<<<B_II + B_UU + B_UI, TPB>>>(ptr_ii, pk_ii, p_ii1, out_ii,
                                        ptr_uu, pk_uu, p_uu1, out_uu,
                                        ptr_ui, pk_ui, p_ego_a, p_ego_b, p_acc);
    k_ui2<<<B_UI, TPB>>>(ptr_ui, pk_ui, p_ego_b, p_ego_a, p_acc);
    k_ui3<<<B_UI, TPB>>>(ptr_ui, pk_ui, p_ego_a, p_acc,
                         out_uu, out_ii, out_u, out_i);
}

// round 5
// speedup vs baseline: 2.1445x; 1.2305x over previous
#include <cuda_runtime.h>
#include <cuda_fp16.h>
#include <cstdint>

#define N_USERS 100000
#define N_ITEMS 40000
#define DIM     64
#define NTOT    (N_USERS + N_ITEMS)
#define VPR     16                 // float4 per row
#define HPR     8                  // uint4 (8 halves each) per fp16 row
#define NNZ_UI_MAX 1500000
#define NNZ_II_MAX 1000000
#define NNZ_UU_MAX 1500000

#define RPB  32                    // rows per 256-thread block (8 lanes/row)
#define B_II (N_ITEMS / RPB)       // 1250
#define B_UU (N_USERS / RPB)       // 3125
#define B_UI (NTOT   / RPB)        // 4375

// -------- scratch (allocation-free: __device__ globals) --------
__device__ uint4  g_iih [N_ITEMS * HPR];
__device__ uint4  g_uuh [N_USERS * HPR];
__device__ uint4  g_ii1h[N_ITEMS * HPR];
__device__ uint4  g_uu1h[N_USERS * HPR];
__device__ uint4  g_egoh_a[NTOT * HPR];
__device__ uint4  g_egoh_b[NTOT * HPR];
__device__ float4 g_acc[NTOT * VPR];

__device__ int    g_ptr_ui[NTOT + 1];
__device__ float2 g_pk_ui[NNZ_UI_MAX];   // (.x = int bits of col*HPR, .y = val)
__device__ int    g_rk_ui[NNZ_UI_MAX];
__device__ int    g_ptr_ii[N_ITEMS + 1];
__device__ float2 g_pk_ii[NNZ_II_MAX];
__device__ int    g_rk_ii[NNZ_II_MAX];
__device__ int    g_ptr_uu[N_USERS + 1];
__device__ float2 g_pk_uu[NNZ_UU_MAX];
__device__ int    g_rk_uu[NNZ_UU_MAX];

// -------- helpers --------
__device__ __forceinline__ uint4 pack8(float4 a, float4 b) {
    uint4 o;
    __half2* h = (__half2*)&o;
    h[0] = __float22half2_rn(make_float2(a.x, a.y));
    h[1] = __float22half2_rn(make_float2(a.z, a.w));
    h[2] = __float22half2_rn(make_float2(b.x, b.y));
    h[3] = __float22half2_rn(make_float2(b.z, b.w));
    return o;
}

__device__ __forceinline__ void fma8(float* s, uint4 g, float w) {
    const __half2* h = (const __half2*)&g;
    float2 f0 = __half22float2(h[0]);
    float2 f1 = __half22float2(h[1]);
    float2 f2 = __half22float2(h[2]);
    float2 f3 = __half22float2(h[3]);
    s[0] += w * f0.x; s[1] += w * f0.y; s[2] += w * f1.x; s[3] += w * f1.y;
    s[4] += w * f2.x; s[5] += w * f2.y; s[6] += w * f3.x; s[7] += w * f3.y;
}

// 8 lanes/row; lane c holds halves [8c, 8c+8)
__device__ __forceinline__ void spmm_row_h(const int* __restrict__ ptr,
                                           const float2* __restrict__ pk,
                                           const uint4* __restrict__ xh,
                                           int r, int c, float* s) {
    #pragma unroll
    for (int k = 0; k < 8; ++k) s[k] = 0.f;
    int j = __ldg(ptr + r);
    int end = __ldg(ptr + r + 1);
    for (; j + 4 <= end; j += 4) {
        float2 p0 = __ldg(pk + j + 0);
        float2 p1 = __ldg(pk + j + 1);
        float2 p2 = __ldg(pk + j + 2);
        float2 p3 = __ldg(pk + j + 3);
        uint4 g0 = __ldg(xh + __float_as_int(p0.x) + c);
        uint4 g1 = __ldg(xh + __float_as_int(p1.x) + c);
        uint4 g2 = __ldg(xh + __float_as_int(p2.x) + c);
        uint4 g3 = __ldg(xh + __float_as_int(p3.x) + c);
        fma8(s, g0, p0.y); fma8(s, g1, p1.y); fma8(s, g2, p2.y); fma8(s, g3, p3.y);
    }
    for (; j < end; ++j) {
        float2 p = __ldg(pk + j);
        uint4 g = __ldg(xh + __float_as_int(p.x) + c);
        fma8(s, g, p.y);
    }
}

__device__ __forceinline__ void store_h(uint4* __restrict__ yh, int r, int c,
                                        const float* s) {
    uint4 o;
    __half2* h = (__half2*)&o;
    h[0] = __float22half2_rn(make_float2(s[0], s[1]));
    h[1] = __float22half2_rn(make_float2(s[2], s[3]));
    h[2] = __float22half2_rn(make_float2(s[4], s[5]));
    h[3] = __float22half2_rn(make_float2(s[6], s[7]));
    yh[(size_t)r * HPR + c] = o;
}

__device__ __forceinline__ void store_f(float4* __restrict__ y, int r, int c,
                                        const float* s) {
    size_t b = (size_t)r * VPR + 2 * c;
    y[b]     = make_float4(s[0], s[1], s[2], s[3]);
    y[b + 1] = make_float4(s[4], s[5], s[6], s[7]);
}

__device__ __forceinline__ void acc_add(float4* __restrict__ acc, int r, int c,
                                        const float* s) {
    size_t b = (size_t)r * VPR + 2 * c;
    float4 a0 = acc[b], a1 = acc[b + 1];
    acc[b]     = make_float4(a0.x + s[0], a0.y + s[1], a0.z + s[2], a0.w + s[3]);
    acc[b + 1] = make_float4(a1.x + s[4], a1.y + s[5], a1.z + s[6], a1.w + s[7]);
}

// -------- convert inputs to fp16 + seed acc (independent of CSR build) --------
#define CVT_EGO (NTOT   * HPR)
#define CVT_II  (N_ITEMS * HPR)
#define CVT_UU  (N_USERS * HPR)

__global__ __launch_bounds__(256) void k_cvt(const float4* __restrict__ u,
                                             const float4* __restrict__ it,
                                             const float4* __restrict__ ii,
                                             const float4* __restrict__ uu,
                                             uint4* __restrict__ egoh,
                                             float4* __restrict__ acc,
                                             uint4* __restrict__ iih,
                                             uint4* __restrict__ uuh) {
    int i = blockIdx.x * 256 + threadIdx.x;
    if (i < CVT_EGO) {
        float4 a0, a1;
        if (i < N_USERS * HPR) {
            a0 = __ldg(u + 2 * i); a1 = __ldg(u + 2 * i + 1);
        } else {
            int t = 2 * i - N_USERS * VPR;
            a0 = __ldg(it + t); a1 = __ldg(it + t + 1);
        }
        acc[2 * i] = a0; acc[2 * i + 1] = a1;
        egoh[i] = pack8(a0, a1);
    }
    if (i < CVT_II) iih[i] = pack8(__ldg(ii + 2 * i), __ldg(ii + 2 * i + 1));
    if (i < CVT_UU) uuh[i] = pack8(__ldg(uu + 2 * i), __ldg(uu + 2 * i + 1));
}

// -------- fused CSR build --------
__global__ __launch_bounds__(256) void k_zero3(int* __restrict__ a, int na,
                                               int* __restrict__ b, int nb,
                                               int* __restrict__ c, int nc) {
    int i = blockIdx.x * blockDim.x + threadIdx.x;
    if (i < na) a[i] = 0;
    if (i < nb) b[i] = 0;
    if (i < nc) c[i] = 0;
}

// histogram + record each edge's within-row rank; 2 edges per thread for MLP
__global__ __launch_bounds__(256) void k_hist3(
        const int* __restrict__ r0, int n0, int* __restrict__ c0, int* __restrict__ k0,
        const int* __restrict__ r1, int n1, int* __restrict__ c1, int* __restrict__ k1,
        const int* __restrict__ r2, int n2, int* __restrict__ c2, int* __restrict__ k2) {
    int base = blockIdx.x * 512 + threadIdx.x;
    #pragma unroll
    for (int u = 0; u < 2; ++u) {
        int i = base + u * 256;
        if (i < n0) k0[i] = atomicAdd(c0 + __ldg(r0 + i), 1);
        if (i < n1) k1[i] = atomicAdd(c1 + __ldg(r1 + i), 1);
        if (i < n2) k2[i] = atomicAdd(c2 + __ldg(r2 + i), 1);
    }
}

// 3 blocks, one per matrix: exclusive scan of cnt in place, cnt[n] = total.
__global__ __launch_bounds__(1024) void k_scan3(int* __restrict__ cA, int nA,
                                                int* __restrict__ cB, int nB,
                                                int* __restrict__ cC, int nC) {
    int* cnt; int n;
    if (blockIdx.x == 0) { cnt = cA; n = nA; }
    else if (blockIdx.x == 1) { cnt = cB; n = nB; }
    else { cnt = cC; n = nC; }

    __shared__ int sh[1024];
    int t = threadIdx.x;
    int chunk = (n + 1023) >> 10;
    int lo = t * chunk, hi = min(lo + chunk, n);
    int s = 0;
    for (int i = lo; i < hi; ++i) s += cnt[i];
    sh[t] = s;
    __syncthreads();
    #pragma unroll
    for (int off = 1; off < 1024; off <<= 1) {
        int v = (t >= off) ? sh[t - off] : 0;
        __syncthreads();
        sh[t] += v;
        __syncthreads();
    }
    int total = sh[1023];
    int run = (t == 0) ? 0 : sh[t - 1];
    for (int i = lo; i < hi; ++i) {
        int c = cnt[i];
        cnt[i] = run;
        run += c;
    }
    if (t == 0) cnt[n] = total;
}

// scatter without atomics: pos = ptr[row] + rank[i]; 2 edges/thread for MLP
__global__ __launch_bounds__(256) void k_scatter3(
        const int* __restrict__ r0, const int* __restrict__ c0, const float* __restrict__ v0,
        const int* __restrict__ ptr0, const int* __restrict__ k0, float2* __restrict__ p0, int n0,
        const int* __restrict__ r1, const int* __restrict__ c1, const float* __restrict__ v1,
        const int* __restrict__ ptr1, const int* __restrict__ k1, float2* __restrict__ p1, int n1,
        const int* __restrict__ r2, const int* __restrict__ c2, const float* __restrict__ v2,
        const int* __restrict__ ptr2, const int* __restrict__ k2, float2* __restrict__ p2, int n2) {
    int base = blockIdx.x * 512 + threadIdx.x;
    #pragma unroll
    for (int u = 0; u < 2; ++u) {
        int i = base + u * 256;
        if (i < n0) {
            int pos = __ldg(ptr0 + __ldg(r0 + i)) + __ldg(k0 + i);
            p0[pos] = make_float2(__int_as_float(__ldg(c0 + i) * HPR), __ldg(v0 + i));
        }
        if (i < n1) {
            int pos = __ldg(ptr1 + __ldg(r1 + i)) + __ldg(k1 + i);
            p1[pos] = make_float2(__int_as_float(__ldg(c1 + i) * HPR), __ldg(v1 + i));
        }
        if (i < n2) {
            int pos = __ldg(ptr2 + __ldg(r2 + i)) + __ldg(k2 + i);
            p2[pos] = make_float2(__int_as_float(__ldg(c2 + i) * HPR), __ldg(v2 + i));
        }
    }
}

// -------- propagation --------
// mix1: ii layer1 | uu layer1 (fp16 -> fp16)
__global__ __launch_bounds__(256) void k_mix1(const int* __restrict__ ptr_ii,
                                              const float2* __restrict__ pk_ii,
                                              const uint4* __restrict__ iih,
                                              uint4* __restrict__ ii1h,
                                              const int* __restrict__ ptr_uu,
                                              const float2* __restrict__ pk_uu,
                                              const uint4* __restrict__ uuh,
                                              uint4* __restrict__ uu1h) {
    int b = blockIdx.x;
    int c = threadIdx.x & 7;
    int rr = threadIdx.x >> 3;
    float s[8];
    if (b < B_II) {
        int r = b * RPB + rr;
        spmm_row_h(ptr_ii, pk_ii, iih, r, c, s);
        store_h(ii1h, r, c, s);
    } else {
        int r = (b - B_II) * RPB + rr;
        spmm_row_h(ptr_uu, pk_uu, uuh, r, c, s);
        store_h(uu1h, r, c, s);
    }
}

// mix2: ii layer2 -> out_ii (fp32) | uu layer2 -> out_uu (fp32) | ui layer1
__global__ __launch_bounds__(256) void k_mix2(const int* __restrict__ ptr_ii,
                                              const float2* __restrict__ pk_ii,
                                              const uint4* __restrict__ ii1h,
                                              float4* __restrict__ out_ii,
                                              const int* __restrict__ ptr_uu,
                                              const float2* __restrict__ pk_uu,
                                              const uint4* __restrict__ uu1h,
                                              float4* __restrict__ out_uu,
                                              const int* __restrict__ ptr_ui,
                                              const float2* __restrict__ pk_ui,
                                              const uint4* __restrict__ egoh_a,
                                              uint4* __restrict__ egoh_b,
                                              float4* __restrict__ acc) {
    int b = blockIdx.x;
    int c = threadIdx.x & 7;
    int rr = threadIdx.x >> 3;
    float s[8];
    if (b < B_II) {
        int r = b * RPB + rr;
        spmm_row_h(ptr_ii, pk_ii, ii1h, r, c, s);
        store_f(out_ii, r, c, s);
    } else if (b < B_II + B_UU) {
        int r = (b - B_II) * RPB + rr;
        spmm_row_h(ptr_uu, pk_uu, uu1h, r, c, s);
        store_f(out_uu, r, c, s);
    } else {
        int r = (b - B_II - B_UU) * RPB + rr;
        spmm_row_h(ptr_ui, pk_ui, egoh_a, r, c, s);
        store_h(egoh_b, r, c, s);
        acc_add(acc, r, c, s);
    }
}

// ui layer2
__global__ __launch_bounds__(256) void k_ui2(const int* __restrict__ ptr_ui,
                                             const float2* __restrict__ pk_ui,
                                             const uint4* __restrict__ egoh_b,
                                             uint4* __restrict__ egoh_a,
                                             float4* __restrict__ acc) {
    int r = blockIdx.x * RPB + (threadIdx.x >> 3);
    int c = threadIdx.x & 7;
    float s[8];
    spmm_row_h(ptr_ui, pk_ui, egoh_b, r, c, s);
    store_h(egoh_a, r, c, s);
    acc_add(acc, r, c, s);
}

// ui layer3 fused with finalize:
// out = (acc + s)/4 + l2_normalize(g), g = out_uu (users) / out_ii (items)
__global__ __launch_bounds__(256) void k_ui3(const int* __restrict__ ptr_ui,
                                             const float2* __restrict__ pk_ui,
                                             const uint4* __restrict__ egoh_a,
                                             const float4* __restrict__ acc,
                                             const float4* __restrict__ out_uu,
                                             const float4* __restrict__ out_ii,
                                             float4* __restrict__ out_u,
                                             float4* __restrict__ out_i) {
    int r = blockIdx.x * RPB + (threadIdx.x >> 3);
    int c = threadIdx.x & 7;
    float s[8];
    spmm_row_h(ptr_ui, pk_ui, egoh_a, r, c, s);

    size_t b = (size_t)r * VPR + 2 * c;
    float4 a0 = __ldg(acc + b), a1 = __ldg(acc + b + 1);
    float o0 = (a0.x + s[0]) * 0.25f, o1 = (a0.y + s[1]) * 0.25f;
    float o2 = (a0.z + s[2]) * 0.25f, o3 = (a0.w + s[3]) * 0.25f;
    float o4 = (a1.x + s[4]) * 0.25f, o5 = (a1.y + s[5]) * 0.25f;
    float o6 = (a1.z + s[6]) * 0.25f, o7 = (a1.w + s[7]) * 0.25f;

    const float4* g = (r < N_USERS) ? (out_uu + (size_t)r * VPR)
                                    : (out_ii + (size_t)(r - N_USERS) * VPR);
    float4 g0 = __ldg(g + 2 * c), g1 = __ldg(g + 2 * c + 1);
    float d = g0.x * g0.x + g0.y * g0.y + g0.z * g0.z + g0.w * g0.w
            + g1.x * g1.x + g1.y * g1.y + g1.z * g1.z + g1.w * g1.w;
    #pragma unroll
    for (int o = 4; o; o >>= 1) d += __shfl_xor_sync(0xffffffffu, d, o, 8);
    float scale = 1.0f / fmaxf(sqrtf(d), 1e-12f);

    float4* ob = (r < N_USERS) ? (out_u + (size_t)r * VPR)
                               : (out_i + (size_t)(r - N_USERS) * VPR);
    ob[2 * c]     = make_float4(o0 + g0.x * scale, o1 + g0.y * scale,
                                o2 + g0.z * scale, o3 + g0.w * scale);
    ob[2 * c + 1] = make_float4(o4 + g1.x * scale, o5 + g1.y * scale,
                                o6 + g1.z * scale, o7 + g1.w * scale);
}

// -------- host orchestration --------
static inline int gridFor(long long threads, int tpb) {
    return (int)((threads + tpb - 1) / tpb);
}

extern "C" void kernel_launch(void* const* d_in, const int* in_sizes, int n_in,
                              void* d_out, int out_size) {
    const float4* user_emb = (const float4*)d_in[0];
    const float4* item_emb = (const float4*)d_in[1];
    const float4* uu_emb   = (const float4*)d_in[2];
    const float4* ii_emb   = (const float4*)d_in[3];
    const float*  ui_vals  = (const float*)d_in[4];
    const float*  ii_vals  = (const float*)d_in[5];
    const float*  uu_vals  = (const float*)d_in[6];
    const int*    ui_rows  = (const int*)d_in[7];
    const int*    ui_cols  = (const int*)d_in[8];
    const int*    ii_rows  = (const int*)d_in[9];
    const int*    ii_cols  = (const int*)d_in[10];
    const int*    uu_rows  = (const int*)d_in[11];
    const int*    uu_cols  = (const int*)d_in[12];
    const int nnz_ui = in_sizes[7];
    const int nnz_ii = in_sizes[9];
    const int nnz_uu = in_sizes[11];

    float* out = (float*)d_out;
    float4* out_u  = (float4*)out;
    float4* out_i  = (float4*)(out + (size_t)N_USERS * DIM);
    float4* out_ii = (float4*)(out + (size_t)(N_USERS + N_ITEMS) * DIM);
    float4* out_uu = (float4*)(out + (size_t)(N_USERS + 2 * N_ITEMS) * DIM);

    uint4 *p_iih, *p_uuh, *p_ii1h, *p_uu1h, *p_egoh_a, *p_egoh_b;
    float4* p_acc;
    cudaGetSymbolAddress((void**)&p_iih,    g_iih);
    cudaGetSymbolAddress((void**)&p_uuh,    g_uuh);
    cudaGetSymbolAddress((void**)&p_ii1h,   g_ii1h);
    cudaGetSymbolAddress((void**)&p_uu1h,   g_uu1h);
    cudaGetSymbolAddress((void**)&p_egoh_a, g_egoh_a);
    cudaGetSymbolAddress((void**)&p_egoh_b, g_egoh_b);
    cudaGetSymbolAddress((void**)&p_acc,    g_acc);
    int *ptr_ui, *ptr_ii, *ptr_uu, *rk_ui, *rk_ii, *rk_uu;
    float2 *pk_ui, *pk_ii, *pk_uu;
    cudaGetSymbolAddress((void**)&ptr_ui, g_ptr_ui);
    cudaGetSymbolAddress((void**)&pk_ui,  g_pk_ui);
    cudaGetSymbolAddress((void**)&rk_ui,  g_rk_ui);
    cudaGetSymbolAddress((void**)&ptr_ii, g_ptr_ii);
    cudaGetSymbolAddress((void**)&pk_ii,  g_pk_ii);
    cudaGetSymbolAddress((void**)&rk_ii,  g_rk_ii);
    cudaGetSymbolAddress((void**)&ptr_uu, g_ptr_uu);
    cudaGetSymbolAddress((void**)&pk_uu,  g_pk_uu);
    cudaGetSymbolAddress((void**)&rk_uu,  g_rk_uu);

    const int TPB = 256;
    const int nnz_max = max(max(nnz_ui, nnz_ii), nnz_uu);

    // ---- convert inputs to fp16, seed acc ----
    k_cvt<<<gridFor(CVT_EGO, TPB), TPB>>>(user_emb, item_emb, ii_emb, uu_emb,
                                          p_egoh_a, p_acc, p_iih, p_uuh);

    // ---- fused CSR build (atomic-free scatter) ----
    k_zero3<<<gridFor(NTOT + 1, TPB), TPB>>>(ptr_ui, NTOT + 1,
                                             ptr_ii, N_ITEMS + 1,
                                             ptr_uu, N_USERS + 1);
    k_hist3<<<gridFor(nnz_max, 512), TPB>>>(ui_rows, nnz_ui, ptr_ui, rk_ui,
                                            ii_rows, nnz_ii, ptr_ii, rk_ii,
                                            uu_rows, nnz_uu, ptr_uu, rk_uu);
    k_scan3<<<3, 1024>>>(ptr_ui, NTOT, ptr_ii, N_ITEMS, ptr_uu, N_USERS);
    k_scatter3<<<gridFor(nnz_max, 512), TPB>>>(
        ui_rows, ui_cols, ui_vals, ptr_ui, rk_ui, pk_ui, nnz_ui,
        ii_rows, ii_cols, ii_vals, ptr_ii, rk_ii, pk_ii, nnz_ii,
        uu_rows, uu_cols, uu_vals, ptr_uu, rk_uu, pk_uu, nnz_uu);

    // ---- propagation ----
    k_mix1<<<B_II + B_UU, TPB>>>(ptr_ii, pk_ii, p_iih, p_ii1h,
                                 ptr_uu, pk_uu, p_uuh, p_uu1h);
    k_mix2<<<B_II + B_UU + B_UI, TPB>>>(ptr_ii, pk_ii, p_ii1h, out_ii,
                                        ptr_uu, pk_uu, p_uu1h, out_uu,
                                        ptr_ui, pk_ui, p_egoh_a, p_egoh_b, p_acc);
    k_ui2<<<B_UI, TPB>>>(ptr_ui, pk_ui, p_egoh_b, p_egoh_a, p_acc);
    k_ui3<<<B_UI, TPB>>>(ptr_ui, pk_ui, p_egoh_a, p_acc,
                         out_uu, out_ii, out_u, out_i);
}

// round 6
// speedup vs baseline: 2.9905x; 1.3945x over previous
#include <cuda_runtime.h>
#include <cuda_fp16.h>
#include <cstdint>

#define N_USERS 100000
#define N_ITEMS 40000
#define DIM     64
#define NTOT    (N_USERS + N_ITEMS)
#define VPR     16                 // float4 per row
#define HPR     8                  // uint4 (8 halves each) per fp16 row
#define NNZ_UI_MAX 1500000
#define NNZ_II_MAX 1000000
#define NNZ_UU_MAX 1500000

#define RPB  32                    // rows per 256-thread block (8 lanes/row)
#define B_II (N_ITEMS / RPB)       // 1250
#define B_UU (N_USERS / RPB)       // 3125
#define B_UI (NTOT   / RPB)        // 4375

// scan tiling
#define SCAN_TILE 2048
#define NB_UI ((NTOT + 1 + SCAN_TILE - 1) / SCAN_TILE)     // 69
#define NB_II ((N_ITEMS + 1 + SCAN_TILE - 1) / SCAN_TILE)  // 20
#define NB_UU ((N_USERS + 1 + SCAN_TILE - 1) / SCAN_TILE)  // 49
#define NB_ALL (NB_UI + NB_II + NB_UU)                     // 138

// -------- scratch (allocation-free: __device__ globals) --------
__device__ uint4  g_iih [N_ITEMS * HPR];
__device__ uint4  g_uuh [N_USERS * HPR];
__device__ uint4  g_ii1h[N_ITEMS * HPR];
__device__ uint4  g_uu1h[N_USERS * HPR];
__device__ uint4  g_egoh_a[NTOT * HPR];
__device__ uint4  g_egoh_b[NTOT * HPR];
__device__ float4 g_acc[NTOT * VPR];

__device__ int    g_ptr_ui[NTOT + 1];
__device__ float2 g_pk_ui[NNZ_UI_MAX];   // (.x = int bits of col*HPR, .y = val)
__device__ int    g_rk_ui[NNZ_UI_MAX];
__device__ int    g_ptr_ii[N_ITEMS + 1];
__device__ float2 g_pk_ii[NNZ_II_MAX];
__device__ int    g_rk_ii[NNZ_II_MAX];
__device__ int    g_ptr_uu[N_USERS + 1];
__device__ float2 g_pk_uu[NNZ_UU_MAX];
__device__ int    g_rk_uu[NNZ_UU_MAX];
__device__ int    g_bsum[NB_ALL];

// -------- helpers --------
__device__ __forceinline__ uint4 pack8(float4 a, float4 b) {
    uint4 o;
    __half2* h = (__half2*)&o;
    h[0] = __float22half2_rn(make_float2(a.x, a.y));
    h[1] = __float22half2_rn(make_float2(a.z, a.w));
    h[2] = __float22half2_rn(make_float2(b.x, b.y));
    h[3] = __float22half2_rn(make_float2(b.z, b.w));
    return o;
}

__device__ __forceinline__ void fma8(float* s, uint4 g, float w) {
    const __half2* h = (const __half2*)&g;
    float2 f0 = __half22float2(h[0]);
    float2 f1 = __half22float2(h[1]);
    float2 f2 = __half22float2(h[2]);
    float2 f3 = __half22float2(h[3]);
    s[0] += w * f0.x; s[1] += w * f0.y; s[2] += w * f1.x; s[3] += w * f1.y;
    s[4] += w * f2.x; s[5] += w * f2.y; s[6] += w * f3.x; s[7] += w * f3.y;
}

// 8 lanes/row; lane c holds halves [8c, 8c+8)
__device__ __forceinline__ void spmm_row_h(const int* __restrict__ ptr,
                                           const float2* __restrict__ pk,
                                           const uint4* __restrict__ xh,
                                           int r, int c, float* s) {
    #pragma unroll
    for (int k = 0; k < 8; ++k) s[k] = 0.f;
    int j = __ldg(ptr + r);
    int end = __ldg(ptr + r + 1);
    for (; j + 4 <= end; j += 4) {
        float2 p0 = __ldg(pk + j + 0);
        float2 p1 = __ldg(pk + j + 1);
        float2 p2 = __ldg(pk + j + 2);
        float2 p3 = __ldg(pk + j + 3);
        uint4 g0 = __ldg(xh + __float_as_int(p0.x) + c);
        uint4 g1 = __ldg(xh + __float_as_int(p1.x) + c);
        uint4 g2 = __ldg(xh + __float_as_int(p2.x) + c);
        uint4 g3 = __ldg(xh + __float_as_int(p3.x) + c);
        fma8(s, g0, p0.y); fma8(s, g1, p1.y); fma8(s, g2, p2.y); fma8(s, g3, p3.y);
    }
    for (; j < end; ++j) {
        float2 p = __ldg(pk + j);
        uint4 g = __ldg(xh + __float_as_int(p.x) + c);
        fma8(s, g, p.y);
    }
}

__device__ __forceinline__ void store_h(uint4* __restrict__ yh, int r, int c,
                                        const float* s) {
    uint4 o;
    __half2* h = (__half2*)&o;
    h[0] = __float22half2_rn(make_float2(s[0], s[1]));
    h[1] = __float22half2_rn(make_float2(s[2], s[3]));
    h[2] = __float22half2_rn(make_float2(s[4], s[5]));
    h[3] = __float22half2_rn(make_float2(s[6], s[7]));
    yh[(size_t)r * HPR + c] = o;
}

__device__ __forceinline__ void store_f(float4* __restrict__ y, int r, int c,
                                        const float* s) {
    size_t b = (size_t)r * VPR + 2 * c;
    y[b]     = make_float4(s[0], s[1], s[2], s[3]);
    y[b + 1] = make_float4(s[4], s[5], s[6], s[7]);
}

__device__ __forceinline__ void acc_add(float4* __restrict__ acc, int r, int c,
                                        const float* s) {
    size_t b = (size_t)r * VPR + 2 * c;
    float4 a0 = acc[b], a1 = acc[b + 1];
    acc[b]     = make_float4(a0.x + s[0], a0.y + s[1], a0.z + s[2], a0.w + s[3]);
    acc[b + 1] = make_float4(a1.x + s[4], a1.y + s[5], a1.z + s[6], a1.w + s[7]);
}

// -------- convert inputs to fp16 + seed acc --------
#define CVT_EGO (NTOT   * HPR)
#define CVT_II  (N_ITEMS * HPR)
#define CVT_UU  (N_USERS * HPR)

__global__ __launch_bounds__(256) void k_cvt(const float4* __restrict__ u,
                                             const float4* __restrict__ it,
                                             const float4* __restrict__ ii,
                                             const float4* __restrict__ uu,
                                             uint4* __restrict__ egoh,
                                             float4* __restrict__ acc,
                                             uint4* __restrict__ iih,
                                             uint4* __restrict__ uuh) {
    int i = blockIdx.x * 256 + threadIdx.x;
    if (i < CVT_EGO) {
        float4 a0, a1;
        if (i < N_USERS * HPR) {
            a0 = __ldg(u + 2 * i); a1 = __ldg(u + 2 * i + 1);
        } else {
            int t = 2 * i - N_USERS * VPR;
            a0 = __ldg(it + t); a1 = __ldg(it + t + 1);
        }
        acc[2 * i] = a0; acc[2 * i + 1] = a1;
        egoh[i] = pack8(a0, a1);
    }
    if (i < CVT_II) iih[i] = pack8(__ldg(ii + 2 * i), __ldg(ii + 2 * i + 1));
    if (i < CVT_UU) uuh[i] = pack8(__ldg(uu + 2 * i), __ldg(uu + 2 * i + 1));
}

// -------- fused CSR build --------
__global__ __launch_bounds__(256) void k_zero3(int* __restrict__ a, int na,
                                               int* __restrict__ b, int nb,
                                               int* __restrict__ c, int nc) {
    int i = blockIdx.x * blockDim.x + threadIdx.x;
    if (i < na) a[i] = 0;
    if (i < nb) b[i] = 0;
    if (i < nc) c[i] = 0;
}

// histogram + record each edge's within-row rank; 2 edges per thread for MLP
__global__ __launch_bounds__(256) void k_hist3(
        const int* __restrict__ r0, int n0, int* __restrict__ c0, int* __restrict__ k0,
        const int* __restrict__ r1, int n1, int* __restrict__ c1, int* __restrict__ k1,
        const int* __restrict__ r2, int n2, int* __restrict__ c2, int* __restrict__ k2) {
    int base = blockIdx.x * 512 + threadIdx.x;
    #pragma unroll
    for (int u = 0; u < 2; ++u) {
        int i = base + u * 256;
        if (i < n0) k0[i] = atomicAdd(c0 + __ldg(r0 + i), 1);
        if (i < n1) k1[i] = atomicAdd(c1 + __ldg(r1 + i), 1);
        if (i < n2) k2[i] = atomicAdd(c2 + __ldg(r2 + i), 1);
    }
}

// -------- 3-phase multi-block exclusive scan of the 3 ptr arrays --------
// block b covers a 2048-elem tile; scanning n+1 elems makes ptr[n]=total.
__device__ __forceinline__ void scan_map(int b, int** cnt, int* n, int* blk) {
    int *pu, *pi, *pw;
    // resolved by caller passing globals; placeholder (unused)
    (void)b; (void)cnt; (void)n; (void)blk; (void)pu; (void)pi; (void)pw;
}

__global__ __launch_bounds__(1024) void k_scan_blk(int* __restrict__ cui,
                                                   int* __restrict__ cii,
                                                   int* __restrict__ cuu,
                                                   int* __restrict__ bsum) {
    int b = blockIdx.x;
    int* cnt; int n; int lb;
    if (b < NB_UI)              { cnt = cui; n = NTOT + 1;    lb = b; }
    else if (b < NB_UI + NB_II) { cnt = cii; n = N_ITEMS + 1; lb = b - NB_UI; }
    else                        { cnt = cuu; n = N_USERS + 1; lb = b - NB_UI - NB_II; }
    int base = lb * SCAN_TILE;
    int t = threadIdx.x;
    int i0 = base + 2 * t, i1 = base + 2 * t + 1;
    int x0 = (i0 < n) ? cnt[i0] : 0;
    int x1 = (i1 < n) ? cnt[i1] : 0;
    int pair = x0 + x1;

    __shared__ int sh[1024];
    sh[t] = pair;
    __syncthreads();
    #pragma unroll
    for (int off = 1; off < 1024; off <<= 1) {
        int v = (t >= off) ? sh[t - off] : 0;
        __syncthreads();
        sh[t] += v;
        __syncthreads();
    }
    int excl = sh[t] - pair;
    if (i0 < n) cnt[i0] = excl;
    if (i1 < n) cnt[i1] = excl + x0;
    if (t == 1023) bsum[b] = sh[1023];
}

// 1 block, 3 warps: warp w exclusive-scans its array's block sums in place.
__global__ __launch_bounds__(128) void k_scan_bsums(int* __restrict__ bsum) {
    int w = threadIdx.x >> 5;
    int lane = threadIdx.x & 31;
    if (w >= 3) return;
    int lo = (w == 0) ? 0 : (w == 1) ? NB_UI : NB_UI + NB_II;
    int cnt = (w == 0) ? NB_UI : (w == 1) ? NB_II : NB_UU;
    int carry = 0;
    for (int base = 0; base < cnt; base += 32) {
        int i = base + lane;
        int v = (i < cnt) ? bsum[lo + i] : 0;
        int incl = v;
        #pragma unroll
        for (int o = 1; o < 32; o <<= 1) {
            int u = __shfl_up_sync(0xffffffffu, incl, o);
            if (lane >= o) incl += u;
        }
        if (i < cnt) bsum[lo + i] = incl - v + carry;
        carry += __shfl_sync(0xffffffffu, incl, 31);
    }
}

__global__ __launch_bounds__(1024) void k_scan_add(int* __restrict__ cui,
                                                   int* __restrict__ cii,
                                                   int* __restrict__ cuu,
                                                   const int* __restrict__ bsum) {
    int b = blockIdx.x;
    int* cnt; int n; int lb;
    if (b < NB_UI)              { cnt = cui; n = NTOT + 1;    lb = b; }
    else if (b < NB_UI + NB_II) { cnt = cii; n = N_ITEMS + 1; lb = b - NB_UI; }
    else                        { cnt = cuu; n = N_USERS + 1; lb = b - NB_UI - NB_II; }
    int off = __ldg(bsum + b);
    if (off == 0) return;
    int base = lb * SCAN_TILE;
    int i0 = base + 2 * threadIdx.x, i1 = i0 + 1;
    if (i0 < n) cnt[i0] += off;
    if (i1 < n) cnt[i1] += off;
}

// scatter without atomics: pos = ptr[row] + rank[i]; 2 edges/thread for MLP
__global__ __launch_bounds__(256) void k_scatter3(
        const int* __restrict__ r0, const int* __restrict__ c0, const float* __restrict__ v0,
        const int* __restrict__ ptr0, const int* __restrict__ k0, float2* __restrict__ p0, int n0,
        const int* __restrict__ r1, const int* __restrict__ c1, const float* __restrict__ v1,
        const int* __restrict__ ptr1, const int* __restrict__ k1, float2* __restrict__ p1, int n1,
        const int* __restrict__ r2, const int* __restrict__ c2, const float* __restrict__ v2,
        const int* __restrict__ ptr2, const int* __restrict__ k2, float2* __restrict__ p2, int n2) {
    int base = blockIdx.x * 512 + threadIdx.x;
    #pragma unroll
    for (int u = 0; u < 2; ++u) {
        int i = base + u * 256;
        if (i < n0) {
            int pos = __ldg(ptr0 + __ldg(r0 + i)) + __ldg(k0 + i);
            p0[pos] = make_float2(__int_as_float(__ldg(c0 + i) * HPR), __ldg(v0 + i));
        }
        if (i < n1) {
            int pos = __ldg(ptr1 + __ldg(r1 + i)) + __ldg(k1 + i);
            p1[pos] = make_float2(__int_as_float(__ldg(c1 + i) * HPR), __ldg(v1 + i));
        }
        if (i < n2) {
            int pos = __ldg(ptr2 + __ldg(r2 + i)) + __ldg(k2 + i);
            p2[pos] = make_float2(__int_as_float(__ldg(c2 + i) * HPR), __ldg(v2 + i));
        }
    }
}

// -------- propagation --------
// mix1: ii layer1 | uu layer1 (fp16 -> fp16)
__global__ __launch_bounds__(256) void k_mix1(const int* __restrict__ ptr_ii,
                                              const float2* __restrict__ pk_ii,
                                              const uint4* __restrict__ iih,
                                              uint4* __restrict__ ii1h,
                                              const int* __restrict__ ptr_uu,
                                              const float2* __restrict__ pk_uu,
                                              const uint4* __restrict__ uuh,
                                              uint4* __restrict__ uu1h) {
    int b = blockIdx.x;
    int c = threadIdx.x & 7;
    int rr = threadIdx.x >> 3;
    float s[8];
    if (b < B_II) {
        int r = b * RPB + rr;
        spmm_row_h(ptr_ii, pk_ii, iih, r, c, s);
        store_h(ii1h, r, c, s);
    } else {
        int r = (b - B_II) * RPB + rr;
        spmm_row_h(ptr_uu, pk_uu, uuh, r, c, s);
        store_h(uu1h, r, c, s);
    }
}

// mix2: ii layer2 -> out_ii (fp32) | uu layer2 -> out_uu (fp32) | ui layer1
__global__ __launch_bounds__(256) void k_mix2(const int* __restrict__ ptr_ii,
                                              const float2* __restrict__ pk_ii,
                                              const uint4* __restrict__ ii1h,
                                              float4* __restrict__ out_ii,
                                              const int* __restrict__ ptr_uu,
                                              const float2* __restrict__ pk_uu,
                                              const uint4* __restrict__ uu1h,
                                              float4* __restrict__ out_uu,
                                              const int* __restrict__ ptr_ui,
                                              const float2* __restrict__ pk_ui,
                                              const uint4* __restrict__ egoh_a,
                                              uint4* __restrict__ egoh_b,
                                              float4* __restrict__ acc) {
    int b = blockIdx.x;
    int c = threadIdx.x & 7;
    int rr = threadIdx.x >> 3;
    float s[8];
    if (b < B_II) {
        int r = b * RPB + rr;
        spmm_row_h(ptr_ii, pk_ii, ii1h, r, c, s);
        store_f(out_ii, r, c, s);
    } else if (b < B_II + B_UU) {
        int r = (b - B_II) * RPB + rr;
        spmm_row_h(ptr_uu, pk_uu, uu1h, r, c, s);
        store_f(out_uu, r, c, s);
    } else {
        int r = (b - B_II - B_UU) * RPB + rr;
        spmm_row_h(ptr_ui, pk_ui, egoh_a, r, c, s);
        store_h(egoh_b, r, c, s);
        acc_add(acc, r, c, s);
    }
}

// ui layer2
__global__ __launch_bounds__(256) void k_ui2(const int* __restrict__ ptr_ui,
                                             const float2* __restrict__ pk_ui,
                                             const uint4* __restrict__ egoh_b,
                                             uint4* __restrict__ egoh_a,
                                             float4* __restrict__ acc) {
    int r = blockIdx.x * RPB + (threadIdx.x >> 3);
    int c = threadIdx.x & 7;
    float s[8];
    spmm_row_h(ptr_ui, pk_ui, egoh_b, r, c, s);
    store_h(egoh_a, r, c, s);
    acc_add(acc, r, c, s);
}

// ui layer3 fused with finalize:
// out = (acc + s)/4 + l2_normalize(g), g = out_uu (users) / out_ii (items)
__global__ __launch_bounds__(256) void k_ui3(const int* __restrict__ ptr_ui,
                                             const float2* __restrict__ pk_ui,
                                             const uint4* __restrict__ egoh_a,
                                             const float4* __restrict__ acc,
                                             const float4* __restrict__ out_uu,
                                             const float4* __restrict__ out_ii,
                                             float4* __restrict__ out_u,
                                             float4* __restrict__ out_i) {
    int r = blockIdx.x * RPB + (threadIdx.x >> 3);
    int c = threadIdx.x & 7;
    float s[8];
    spmm_row_h(ptr_ui, pk_ui, egoh_a, r, c, s);

    size_t b = (size_t)r * VPR + 2 * c;
    float4 a0 = __ldg(acc + b), a1 = __ldg(acc + b + 1);
    float o0 = (a0.x + s[0]) * 0.25f, o1 = (a0.y + s[1]) * 0.25f;
    float o2 = (a0.z + s[2]) * 0.25f, o3 = (a0.w + s[3]) * 0.25f;
    float o4 = (a1.x + s[4]) * 0.25f, o5 = (a1.y + s[5]) * 0.25f;
    float o6 = (a1.z + s[6]) * 0.25f, o7 = (a1.w + s[7]) * 0.25f;

    const float4* g = (r < N_USERS) ? (out_uu + (size_t)r * VPR)
                                    : (out_ii + (size_t)(r - N_USERS) * VPR);
    float4 g0 = __ldg(g + 2 * c), g1 = __ldg(g + 2 * c + 1);
    float d = g0.x * g0.x + g0.y * g0.y + g0.z * g0.z + g0.w * g0.w
            + g1.x * g1.x + g1.y * g1.y + g1.z * g1.z + g1.w * g1.w;
    #pragma unroll
    for (int o = 4; o; o >>= 1) d += __shfl_xor_sync(0xffffffffu, d, o, 8);
    float scale = 1.0f / fmaxf(sqrtf(d), 1e-12f);

    float4* ob = (r < N_USERS) ? (out_u + (size_t)r * VPR)
                               : (out_i + (size_t)(r - N_USERS) * VPR);
    ob[2 * c]     = make_float4(o0 + g0.x * scale, o1 + g0.y * scale,
                                o2 + g0.z * scale, o3 + g0.w * scale);
    ob[2 * c + 1] = make_float4(o4 + g1.x * scale, o5 + g1.y * scale,
                                o6 + g1.z * scale, o7 + g1.w * scale);
}

// -------- host orchestration --------
static inline int gridFor(long long threads, int tpb) {
    return (int)((threads + tpb - 1) / tpb);
}

extern "C" void kernel_launch(void* const* d_in, const int* in_sizes, int n_in,
                              void* d_out, int out_size) {
    const float4* user_emb = (const float4*)d_in[0];
    const float4* item_emb = (const float4*)d_in[1];
    const float4* uu_emb   = (const float4*)d_in[2];
    const float4* ii_emb   = (const float4*)d_in[3];
    const float*  ui_vals  = (const float*)d_in[4];
    const float*  ii_vals  = (const float*)d_in[5];
    const float*  uu_vals  = (const float*)d_in[6];
    const int*    ui_rows  = (const int*)d_in[7];
    const int*    ui_cols  = (const int*)d_in[8];
    const int*    ii_rows  = (const int*)d_in[9];
    const int*    ii_cols  = (const int*)d_in[10];
    const int*    uu_rows  = (const int*)d_in[11];
    const int*    uu_cols  = (const int*)d_in[12];
    const int nnz_ui = in_sizes[7];
    const int nnz_ii = in_sizes[9];
    const int nnz_uu = in_sizes[11];

    float* out = (float*)d_out;
    float4* out_u  = (float4*)out;
    float4* out_i  = (float4*)(out + (size_t)N_USERS * DIM);
    float4* out_ii = (float4*)(out + (size_t)(N_USERS + N_ITEMS) * DIM);
    float4* out_uu = (float4*)(out + (size_t)(N_USERS + 2 * N_ITEMS) * DIM);

    uint4 *p_iih, *p_uuh, *p_ii1h, *p_uu1h, *p_egoh_a, *p_egoh_b;
    float4* p_acc;
    cudaGetSymbolAddress((void**)&p_iih,    g_iih);
    cudaGetSymbolAddress((void**)&p_uuh,    g_uuh);
    cudaGetSymbolAddress((void**)&p_ii1h,   g_ii1h);
    cudaGetSymbolAddress((void**)&p_uu1h,   g_uu1h);
    cudaGetSymbolAddress((void**)&p_egoh_a, g_egoh_a);
    cudaGetSymbolAddress((void**)&p_egoh_b, g_egoh_b);
    cudaGetSymbolAddress((void**)&p_acc,    g_acc);
    int *ptr_ui, *ptr_ii, *ptr_uu, *rk_ui, *rk_ii, *rk_uu, *bsum;
    float2 *pk_ui, *pk_ii, *pk_uu;
    cudaGetSymbolAddress((void**)&ptr_ui, g_ptr_ui);
    cudaGetSymbolAddress((void**)&pk_ui,  g_pk_ui);
    cudaGetSymbolAddress((void**)&rk_ui,  g_rk_ui);
    cudaGetSymbolAddress((void**)&ptr_ii, g_ptr_ii);
    cudaGetSymbolAddress((void**)&pk_ii,  g_pk_ii);
    cudaGetSymbolAddress((void**)&rk_ii,  g_rk_ii);
    cudaGetSymbolAddress((void**)&ptr_uu, g_ptr_uu);
    cudaGetSymbolAddress((void**)&pk_uu,  g_pk_uu);
    cudaGetSymbolAddress((void**)&rk_uu,  g_rk_uu);
    cudaGetSymbolAddress((void**)&bsum,   g_bsum);

    const int TPB = 256;
    const int nnz_max = max(max(nnz_ui, nnz_ii), nnz_uu);

    // ---- convert inputs to fp16, seed acc ----
    k_cvt<<<gridFor(CVT_EGO, TPB), TPB>>>(user_emb, item_emb, ii_emb, uu_emb,
                                          p_egoh_a, p_acc, p_iih, p_uuh);

    // ---- fused CSR build (atomic-free scatter, multi-block scan) ----
    k_zero3<<<gridFor(NTOT + 1, TPB), TPB>>>(ptr_ui, NTOT + 1,
                                             ptr_ii, N_ITEMS + 1,
                                             ptr_uu, N_USERS + 1);
    k_hist3<<<gridFor(nnz_max, 512), TPB>>>(ui_rows, nnz_ui, ptr_ui, rk_ui,
                                            ii_rows, nnz_ii, ptr_ii, rk_ii,
                                            uu_rows, nnz_uu, ptr_uu, rk_uu);
    k_scan_blk<<<NB_ALL, 1024>>>(ptr_ui, ptr_ii, ptr_uu, bsum);
    k_scan_bsums<<<1, 128>>>(bsum);
    k_scan_add<<<NB_ALL, 1024>>>(ptr_ui, ptr_ii, ptr_uu, bsum);
    k_scatter3<<<gridFor(nnz_max, 512), TPB>>>(
        ui_rows, ui_cols, ui_vals, ptr_ui, rk_ui, pk_ui, nnz_ui,
        ii_rows, ii_cols, ii_vals, ptr_ii, rk_ii, pk_ii, nnz_ii,
        uu_rows, uu_cols, uu_vals, ptr_uu, rk_uu, pk_uu, nnz_uu);

    // ---- propagation ----
    k_mix1<<<B_II + B_UU, TPB>>>(ptr_ii, pk_ii, p_iih, p_ii1h,
                                 ptr_uu, pk_uu, p_uuh, p_uu1h);
    k_mix2<<<B_II + B_UU + B_UI, TPB>>>(ptr_ii, pk_ii, p_ii1h, out_ii,
                                        ptr_uu, pk_uu, p_uu1h, out_uu,
                                        ptr_ui, pk_ui, p_egoh_a, p_egoh_b, p_acc);
    k_ui2<<<B_UI, TPB>>>(ptr_ui, pk_ui, p_egoh_b, p_egoh_a, p_acc);
    k_ui3<<<B_UI, TPB>>>(ptr_ui, pk_ui, p_egoh_a, p_acc,
                         out_uu, out_ii, out_u, out_i);
}